// round 9
// baseline (speedup 1.0000x reference)
#include <cuda_runtime.h>
#include <cstdint>

#define BB 256
#define SS 512
#define N_IN 2048
#define N_OUT 512
#define HH 30
#define ROWS (BB*SS)   // 131072

// ---------------- device scratch ----------------
__device__ float g_flat[(size_t)ROWS * HH];
__device__ float g_partial[1024 * 64];
__device__ float g_mu[HH];
__device__ float g_rstd[HH];
// pre-converted weights (single rna-tf32), transposed [n][k], pair-permuted within 8-groups
__device__ uint32_t g_w1t[32 * N_IN];      // 256 KB
__device__ uint32_t g_wot[N_OUT * 32];     // 64 KB

// pair permutation within each 8-element k-group: (tg,hi) -> tg*2+hi
__host__ __device__ __forceinline__ int kperm(int k) {
    return (k & ~7) | ((k & 3) << 1) | ((k & 4) >> 2);
}

// ---------------- helpers ----------------
__device__ __forceinline__ uint32_t cvt_tf32(float f) {
    uint32_t u; asm("cvt.rna.tf32.f32 %0, %1;" : "=r"(u) : "f"(f)); return u;
}
__device__ __forceinline__ float cvt_tf32f(float f) {
    return __uint_as_float(cvt_tf32(f));
}
__device__ __forceinline__ void mma_tf32(float& c0, float& c1, float& c2, float& c3,
                                         uint32_t a0, uint32_t a1, uint32_t a2, uint32_t a3,
                                         uint32_t b0, uint32_t b1) {
    asm volatile(
        "mma.sync.aligned.m16n8k8.row.col.f32.tf32.tf32.f32 "
        "{%0,%1,%2,%3},{%4,%5,%6,%7},{%8,%9},{%0,%1,%2,%3};"
        : "+f"(c0), "+f"(c1), "+f"(c2), "+f"(c3)
        : "r"(a0), "r"(a1), "r"(a2), "r"(a3), "r"(b0), "r"(b1));
}
__device__ __forceinline__ float htanh(float x) {
    float r; asm("tanh.approx.f32 %0,%1;" : "=f"(r) : "f"(x)); return r;
}
__device__ __forceinline__ float hsig(float x) {
    return fmaf(htanh(x * 0.5f), 0.5f, 0.5f);
}

// ---------------- prep: W1/Wout -> tf32, transposed, pair-permuted ----------
__global__ __launch_bounds__(256)
void prep_w_kernel(const float* __restrict__ W1, const float* __restrict__ Wout)
{
    int i = blockIdx.x * 256 + threadIdx.x;
    if (i < 32 * N_IN) {
        int k = i >> 5, n = i & 31;
        float w = (n < HH) ? W1[(size_t)k * HH + n] : 0.f;
        g_w1t[n * N_IN + kperm(k)] = cvt_tf32(w);
    }
    int j = i - 32 * N_IN;
    if (j >= 0 && j < N_OUT * 32) {
        int n = j >> 5, k = j & 31;
        float w = (k < HH) ? Wout[(size_t)k * N_OUT + n] : 0.f;
        g_wot[n * 32 + kperm(k)] = cvt_tf32(w);
    }
}

// ================= fc1: tf32 mma.sync, depth-2 prefetch =================
// C[131072,30] = X @ W1; +bias, ReLU, BN partials.
// smem (floats): A[2][128][36] | B[2][32][36] | bias[32] | red[2*256]
#define FC1_A_FL (2*128*36)
#define FC1_B_FL (2*32*36)
#define FC1_SMEM_BYTES ((FC1_A_FL + FC1_B_FL + 32 + 512) * 4)

__global__ __launch_bounds__(256)
void fc1_mma_kernel(const float* __restrict__ x, const float* __restrict__ b1)
{
    extern __shared__ __align__(16) float sm[];
    float* a_s    = sm;                               // [2][128][36] (pair-permuted k)
    float* b_s    = sm + FC1_A_FL;                    // [2][32][36]  (pair-permuted k)
    float* bias_s = sm + FC1_A_FL + FC1_B_FL;         // [32]
    float* red    = bias_s + 32;                      // [2][256]

    const int tid  = threadIdx.x;
    const int wid  = tid >> 5;
    const int lane = tid & 31;
    const int g    = lane >> 2;
    const int tg   = lane & 3;
    const size_t rowBase = (size_t)blockIdx.x * 128;

    if (tid < 32) bias_s[tid] = (tid < HH) ? b1[tid] : 0.f;

    float c[4][4];
    #pragma unroll
    for (int nt = 0; nt < 4; nt++)
        #pragma unroll
        for (int q = 0; q < 4; q++) c[nt][q] = 0.f;

    const int ar = tid >> 1;             // A row 0..127 (2 threads/row)
    const int kb = (tid & 1) * 16;       // k base: 0 or 16
    const int bn = tid >> 3;             // B: n 0..31
    const int bf = tid & 7;              // B: float4 idx 0..7
    float4 pA[3][4];
    float4 pB[3];

    auto prefetch = [&](int j, int s) {
        const float* xp = &x[(rowBase + ar) * (size_t)N_IN + j * 32 + kb];
        #pragma unroll
        for (int q = 0; q < 4; q++) pA[s][q] = *(const float4*)(xp + q * 4);
        const float4* wb = (const float4*)g_w1t;     // per n: N_IN/4 float4
        pB[s] = wb[(size_t)bn * (N_IN / 4) + j * 8 + bf];
    };
    auto store_stage = [&](int st, int s) {
        float* ap = &a_s[st * 4608 + ar * 36];
        float v[16];
        #pragma unroll
        for (int q = 0; q < 4; q++) {
            v[q*4+0] = pA[s][q].x; v[q*4+1] = pA[s][q].y;
            v[q*4+2] = pA[s][q].z; v[q*4+3] = pA[s][q].w;
        }
        #pragma unroll
        for (int grp = 0; grp < 2; grp++) {
            int ksab = (kb >> 3) + grp;
            #pragma unroll
            for (int t2 = 0; t2 < 4; t2++) {
                float2 w2 = make_float2(cvt_tf32f(v[grp*8 + t2]),
                                        cvt_tf32f(v[grp*8 + t2 + 4]));
                *(float2*)&ap[ksab * 8 + t2 * 2] = w2;
            }
        }
        *(float4*)&b_s[st * 1152 + bn * 36 + bf * 4] = pB[s];
    };

    prefetch(0, 0);
    prefetch(1, 1);
    store_stage(0, 0);
    __syncthreads();
    prefetch(2, 2);

    const int mr = wid * 16;
    for (int j = 0; j < 64; j++) {
        const int cur = j & 1, nxt = cur ^ 1;
        if (j < 63) store_stage(nxt, (j + 1) % 3);
        if (j < 61) prefetch(j + 3, j % 3);
        const float* ab  = &a_s[cur * 4608];
        const float* bbp = &b_s[cur * 1152];
        #pragma unroll
        for (int ks = 0; ks < 4; ks++) {
            const int k0 = ks * 8;
            float2 aL = *(const float2*)&ab[(mr + g    ) * 36 + k0 + tg * 2];
            float2 aH = *(const float2*)&ab[(mr + g + 8) * 36 + k0 + tg * 2];
            uint32_t a0 = __float_as_uint(aL.x);
            uint32_t a1 = __float_as_uint(aH.x);
            uint32_t a2 = __float_as_uint(aL.y);
            uint32_t a3 = __float_as_uint(aH.y);
            #pragma unroll
            for (int nt = 0; nt < 4; nt++) {
                float2 f = *(const float2*)&bbp[(nt*8 + g) * 36 + k0 + tg * 2];
                mma_tf32(c[nt][0], c[nt][1], c[nt][2], c[nt][3], a0, a1, a2, a3,
                         __float_as_uint(f.x), __float_as_uint(f.y));
            }
        }
        __syncthreads();
    }

    // epilogue: bias + ReLU + store + BN partials
    size_t r0 = rowBase + wid * 16 + g;
    size_t r1 = r0 + 8;
    #pragma unroll
    for (int nt = 0; nt < 4; nt++) {
        int col = nt * 8 + tg * 2;
        float v00 = 0.f, v01 = 0.f, v10 = 0.f, v11 = 0.f;
        if (col < HH) {
            v00 = fmaxf(c[nt][0] + bias_s[col],     0.f);
            v01 = fmaxf(c[nt][1] + bias_s[col + 1], 0.f);
            v10 = fmaxf(c[nt][2] + bias_s[col],     0.f);
            v11 = fmaxf(c[nt][3] + bias_s[col + 1], 0.f);
            *(float2*)&g_flat[r0 * HH + col] = make_float2(v00, v01);
            *(float2*)&g_flat[r1 * HH + col] = make_float2(v10, v11);
        }
        float s0 = v00 + v10, q0 = v00 * v00 + v10 * v10;
        float s1 = v01 + v11, q1 = v01 * v01 + v11 * v11;
        #pragma unroll
        for (int off = 4; off < 32; off <<= 1) {
            s0 += __shfl_xor_sync(0xffffffffu, s0, off);
            q0 += __shfl_xor_sync(0xffffffffu, q0, off);
            s1 += __shfl_xor_sync(0xffffffffu, s1, off);
            q1 += __shfl_xor_sync(0xffffffffu, q1, off);
        }
        if (g == 0) {
            red[(col    ) * 8 + wid]       = s0;
            red[(col + 1) * 8 + wid]       = s1;
            red[256 + (col    ) * 8 + wid] = q0;
            red[256 + (col + 1) * 8 + wid] = q1;
        }
    }
    __syncthreads();
    if (tid < HH) {
        float s = 0.f, q = 0.f;
        #pragma unroll
        for (int w = 0; w < 8; w++) { s += red[tid * 8 + w]; q += red[256 + tid * 8 + w]; }
        g_partial[blockIdx.x * 60 + tid]      = s;
        g_partial[blockIdx.x * 60 + 30 + tid] = q;
    }
}

// ---------------- BN finalize ----------------
__global__ void bn_stats_kernel()
{
    __shared__ float rs[2][HH][9];
    int c = threadIdx.x & 31;
    int g = threadIdx.x >> 5;
    if (c < HH) {
        float s = 0.f, q = 0.f;
        for (int p = g; p < 1024; p += 8) {
            s += g_partial[p * 60 + c];
            q += g_partial[p * 60 + 30 + c];
        }
        rs[0][c][g] = s; rs[1][c][g] = q;
    }
    __syncthreads();
    if (threadIdx.x < HH) {
        float s = 0.f, q = 0.f;
        #pragma unroll
        for (int g2 = 0; g2 < 8; g2++) { s += rs[0][threadIdx.x][g2]; q += rs[1][threadIdx.x][g2]; }
        const float n = (float)ROWS;
        float mu  = s / n;
        float var = q / n - mu * mu;
        g_mu[threadIdx.x]   = mu;
        g_rstd[threadIdx.x] = rsqrtf(var + 1e-5f);
    }
}

// ---------------- LSTM (R6-proven: scalar dots + MUFU tanh) ----------------
#define LSTM_THREADS 256
#define LSTM_SMEM_FLOATS (SS*32 + 32 + 32 + 32 + 128 + 128 + 32 + 32)
#define LSTM_SMEM_BYTES  (LSTM_SMEM_FLOATS * 4)

__device__ __forceinline__ float dot_step(const float* __restrict__ xv,
                                          const float* __restrict__ hv,
                                          const float (&wi)[32], const float (&wh)[32],
                                          float bj)
{
    const float4* x4 = (const float4*)xv;
    const float4* h4 = (const float4*)hv;
    float a0 = bj, a1 = 0.f, a2 = 0.f, a3 = 0.f;
    float b0 = 0.f, b1 = 0.f, b2 = 0.f, b3 = 0.f;
    #pragma unroll
    for (int q = 0; q < 8; q++) {
        float4 xq = x4[q];
        a0 += wi[4*q+0] * xq.x; a1 += wi[4*q+1] * xq.y;
        a2 += wi[4*q+2] * xq.z; a3 += wi[4*q+3] * xq.w;
        float4 hq = h4[q];
        b0 += wh[4*q+0] * hq.x; b1 += wh[4*q+1] * hq.y;
        b2 += wh[4*q+2] * hq.z; b3 += wh[4*q+3] * hq.w;
    }
    return ((a0 + a1) + (a2 + a3)) + ((b0 + b1) + (b2 + b3));
}

__global__ __launch_bounds__(LSTM_THREADS, 2)
void lstm_kernel(const float* __restrict__ h0, const float* __restrict__ c0,
                 const float* __restrict__ Wih0, const float* __restrict__ Whh0,
                 const float* __restrict__ bias0,
                 const float* __restrict__ Wih1, const float* __restrict__ Whh1,
                 const float* __restrict__ bias1,
                 float* __restrict__ rnn_out)
{
    extern __shared__ __align__(16) float lsm[];
    float* xs    = lsm;                    // [512][32]
    float* h0s   = lsm + SS * 32;          // [32]
    float* h1s   = h0s + 32;               // [32]
    float* y0s   = h1s + 32;               // [32]
    float* z0s   = y0s + 32;               // [128]
    float* z1s   = z0s + 128;              // [128]
    float* mus   = z1s + 128;              // [32]
    float* rstds = mus + 32;               // [32]

    const int tid = threadIdx.x;
    const int b   = blockIdx.x;

    if (tid < 32) {
        mus[tid]   = (tid < HH) ? g_mu[tid]   : 0.f;
        rstds[tid] = (tid < HH) ? g_rstd[tid] : 0.f;
        h0s[tid] = (tid < HH) ? h0[b * HH + tid]            : 0.f;
        h1s[tid] = (tid < HH) ? h0[BB * HH + b * HH + tid]  : 0.f;
        y0s[tid] = 0.f;
    }
    __syncthreads();

    const float* fb = g_flat + (size_t)b * (SS * HH);
    for (int i = tid; i < SS * 32; i += LSTM_THREADS) {
        int s = i >> 5, k = i & 31;
        xs[i] = (k < HH) ? (fb[s * HH + k] - mus[k]) * rstds[k] : 0.f;
    }

    float wi[32], wh[32];
    float bj = 0.f;
    #pragma unroll
    for (int k = 0; k < 32; k++) { wi[k] = 0.f; wh[k] = 0.f; }
    if (tid < 120) {
        #pragma unroll
        for (int k = 0; k < HH; k++) {
            wi[k] = Wih0[tid * HH + k];
            wh[k] = Whh0[tid * HH + k];
        }
        bj = bias0[tid];
    } else if (tid >= 128 && tid < 248) {
        int j = tid - 128;
        #pragma unroll
        for (int k = 0; k < HH; k++) {
            wi[k] = Wih1[j * HH + k];
            wh[k] = Whh1[j * HH + k];
        }
        bj = bias1[j];
    }

    float creg = 0.f;
    if (tid < HH)                          creg = c0[b * HH + tid];
    else if (tid >= 128 && tid < 128+HH)   creg = c0[BB * HH + b * HH + (tid - 128)];

    __syncthreads();

    for (int t = 0; t <= SS; t++) {
        if (t < SS && tid < 120) {
            z0s[tid] = dot_step(xs + t * 32, h0s, wi, wh, bj);
        } else if (t >= 1 && tid >= 128 && tid < 248) {
            z1s[tid - 128] = dot_step(y0s, h1s, wi, wh, bj);
        }
        __syncthreads();
        if (t < SS && tid < HH) {
            float ig = hsig(z0s[tid]);
            float fg = hsig(z0s[30 + tid]);
            float gg = htanh(z0s[60 + tid]);
            float og = hsig(z0s[90 + tid]);
            creg = fg * creg + ig * gg;
            float hh = og * htanh(creg);
            h0s[tid] = hh;
            y0s[tid] = hh;
        } else if (t >= 1 && tid >= 128 && tid < 128 + HH) {
            int u = tid - 128;
            float ig = hsig(z1s[u]);
            float fg = hsig(z1s[30 + u]);
            float gg = htanh(z1s[60 + u]);
            float og = hsig(z1s[90 + u]);
            creg = fg * creg + ig * gg;
            float hh = og * htanh(creg);
            h1s[u] = hh;
            rnn_out[((size_t)b * SS + (t - 1)) * HH + u] = hh;
        }
        __syncthreads();
    }
}

// ================= output GEMM: tf32 mma.sync, 128x128 tiles =================
#define OG_A_FL (128*36)
#define OG_B_FL (128*36)
#define OG_SMEM_BYTES ((OG_A_FL + OG_B_FL) * 4)

__global__ __launch_bounds__(256)
void out_mma_kernel(const float* __restrict__ rnn, const float* __restrict__ bout,
                    float* __restrict__ dorsal)
{
    extern __shared__ __align__(16) float sm[];
    float* a_s = sm;                 // [128][36] (pair-permuted k)
    float* b_s = sm + OG_A_FL;       // [128][36] (pair-permuted k)

    const int tid  = threadIdx.x;
    const int wid  = tid >> 5;
    const int lane = tid & 31;
    const int g    = lane >> 2;
    const int tg   = lane & 3;
    const size_t rb = (size_t)(blockIdx.x >> 2) * 128;
    const int cb    = (blockIdx.x & 3) * 128;

    // A: rnn rows, k padded 30->32, tf32, pair-permuted positions
    for (int i = tid; i < 128 * 32; i += 256) {
        int r = i >> 5, k = i & 31;
        float v = (k < HH) ? rnn[(rb + r) * HH + k] : 0.f;
        a_s[r * 36 + kperm(k)] = cvt_tf32f(v);
    }
    {
        const float4* wb = (const float4*)g_wot;   // 8 float4 per n (already permuted)
        #pragma unroll
        for (int q = 0; q < 4; q++) {
            int idx = q * 256 + tid;               // 0..1023
            int n = idx >> 3, fi = idx & 7;
            float4 v = wb[(size_t)(cb + n) * 8 + fi];
            *(float4*)&b_s[n * 36 + fi * 4] = v;
        }
    }

    float c[16][4];
    #pragma unroll
    for (int nt = 0; nt < 16; nt++) {
        float bv0 = bout[cb + nt * 8 + tg * 2];
        float bv1 = bout[cb + nt * 8 + tg * 2 + 1];
        c[nt][0] = bv0; c[nt][1] = bv1; c[nt][2] = bv0; c[nt][3] = bv1;
    }
    __syncthreads();

    const int mr = wid * 16;
    #pragma unroll
    for (int ks = 0; ks < 4; ks++) {
        const int k0 = ks * 8;
        float2 aL = *(const float2*)&a_s[(mr + g    ) * 36 + k0 + tg * 2];
        float2 aH = *(const float2*)&a_s[(mr + g + 8) * 36 + k0 + tg * 2];
        uint32_t a0 = __float_as_uint(aL.x);
        uint32_t a1 = __float_as_uint(aH.x);
        uint32_t a2 = __float_as_uint(aL.y);
        uint32_t a3 = __float_as_uint(aH.y);
        #pragma unroll
        for (int nt = 0; nt < 16; nt++) {
            float2 f = *(const float2*)&b_s[(nt*8 + g) * 36 + k0 + tg * 2];
            mma_tf32(c[nt][0], c[nt][1], c[nt][2], c[nt][3], a0, a1, a2, a3,
                     __float_as_uint(f.x), __float_as_uint(f.y));
        }
    }

    size_t r0 = rb + wid * 16 + g;
    size_t r1 = r0 + 8;
    #pragma unroll
    for (int nt = 0; nt < 16; nt++) {
        int col = cb + nt * 8 + tg * 2;
        *(float2*)&dorsal[r0 * N_OUT + col] = make_float2(c[nt][0], c[nt][1]);
        *(float2*)&dorsal[r1 * N_OUT + col] = make_float2(c[nt][2], c[nt][3]);
    }
}

// ---------------- launch ----------------
extern "C" void kernel_launch(void* const* d_in, const int* in_sizes, int n_in,
                              void* d_out, int out_size)
{
    const float* x     = (const float*)d_in[0];
    const float* h0    = (const float*)d_in[1];
    const float* c0    = (const float*)d_in[2];
    const float* W1    = (const float*)d_in[3];
    const float* b1    = (const float*)d_in[4];
    const float* Wih0  = (const float*)d_in[5];
    const float* Whh0  = (const float*)d_in[6];
    const float* bias0 = (const float*)d_in[7];
    const float* Wih1  = (const float*)d_in[8];
    const float* Whh1  = (const float*)d_in[9];
    const float* bias1 = (const float*)d_in[10];
    const float* Wout  = (const float*)d_in[11];
    const float* bout  = (const float*)d_in[12];

    float* out    = (float*)d_out;
    float* dorsal = out;
    float* rnn    = out + (size_t)ROWS * N_OUT;

    cudaFuncSetAttribute(fc1_mma_kernel, cudaFuncAttributeMaxDynamicSharedMemorySize,
                         FC1_SMEM_BYTES);
    cudaFuncSetAttribute(out_mma_kernel, cudaFuncAttributeMaxDynamicSharedMemorySize,
                         OG_SMEM_BYTES);
    cudaFuncSetAttribute(lstm_kernel, cudaFuncAttributeMaxDynamicSharedMemorySize,
                         LSTM_SMEM_BYTES);

    prep_w_kernel<<<(32 * N_IN + N_OUT * 32) / 256, 256>>>(W1, Wout);
    fc1_mma_kernel<<<ROWS / 128, 256, FC1_SMEM_BYTES>>>(x, b1);
    bn_stats_kernel<<<1, 256>>>();
    lstm_kernel<<<BB, LSTM_THREADS, LSTM_SMEM_BYTES>>>(h0, c0, Wih0, Whh0, bias0,
                                                       Wih1, Whh1, bias1, rnn);
    out_mma_kernel<<<(ROWS / 128) * (N_OUT / 128), 256, OG_SMEM_BYTES>>>(rnn, bout, dorsal);
}

// round 10
// speedup vs baseline: 1.1844x; 1.1844x over previous
#include <cuda_runtime.h>
#include <cstdint>

#define BB 256
#define SS 512
#define N_IN 2048
#define N_OUT 512
#define HH 30
#define ROWS (BB*SS)   // 131072

// ---------------- device scratch ----------------
__device__ float g_flat[(size_t)ROWS * HH];
__device__ float g_partial[1024 * 64];
__device__ float g_mu[HH];
__device__ float g_rstd[HH];
// pre-converted weights (single rna-tf32), transposed [n][k], pair-permuted within 8-groups
__device__ uint32_t g_w1t[32 * N_IN];      // 256 KB
__device__ uint32_t g_wot[N_OUT * 32];     // 64 KB

// pair permutation within each 8-element k-group: fragment pair (tg, tg+4) -> adjacent
__host__ __device__ __forceinline__ int kperm(int k) {
    return (k & ~7) | ((k & 3) << 1) | ((k & 4) >> 2);
}

// ---------------- helpers ----------------
__device__ __forceinline__ uint32_t cvt_tf32(float f) {
    uint32_t u; asm("cvt.rna.tf32.f32 %0, %1;" : "=r"(u) : "f"(f)); return u;
}
__device__ __forceinline__ float cvt_tf32f(float f) {
    return __uint_as_float(cvt_tf32(f));
}
__device__ __forceinline__ void mma_tf32(float& c0, float& c1, float& c2, float& c3,
                                         uint32_t a0, uint32_t a1, uint32_t a2, uint32_t a3,
                                         uint32_t b0, uint32_t b1) {
    asm volatile(
        "mma.sync.aligned.m16n8k8.row.col.f32.tf32.tf32.f32 "
        "{%0,%1,%2,%3},{%4,%5,%6,%7},{%8,%9},{%0,%1,%2,%3};"
        : "+f"(c0), "+f"(c1), "+f"(c2), "+f"(c3)
        : "r"(a0), "r"(a1), "r"(a2), "r"(a3), "r"(b0), "r"(b1));
}
__device__ __forceinline__ float htanh(float x) {
    float r; asm("tanh.approx.f32 %0,%1;" : "=f"(r) : "f"(x)); return r;
}
__device__ __forceinline__ float hsig(float x) {
    return fmaf(htanh(x * 0.5f), 0.5f, 0.5f);
}

// ---------------- prep: W1/Wout -> tf32, transposed, pair-permuted ----------
__global__ __launch_bounds__(256)
void prep_w_kernel(const float* __restrict__ W1, const float* __restrict__ Wout)
{
    int i = blockIdx.x * 256 + threadIdx.x;
    if (i < 32 * N_IN) {
        int k = i >> 5, n = i & 31;
        float w = (n < HH) ? W1[(size_t)k * HH + n] : 0.f;
        g_w1t[n * N_IN + kperm(k)] = cvt_tf32(w);
    }
    int j = i - 32 * N_IN;
    if (j >= 0 && j < N_OUT * 32) {
        int n = j >> 5, k = j & 31;
        float w = (k < HH) ? Wout[(size_t)k * N_OUT + n] : 0.f;
        g_wot[n * 32 + kperm(k)] = cvt_tf32(w);
    }
}

// ================= fc1: tf32 mma.sync, double-buffered (depth-1, static regs) ==
// C[131072,30] = X @ W1; +bias, ReLU, BN partials.
// smem (floats): A[2][128][36] | B[2][32][36] | bias[32] | red[2*256]
#define FC1_A_FL (2*128*36)
#define FC1_B_FL (2*32*36)
#define FC1_SMEM_BYTES ((FC1_A_FL + FC1_B_FL + 32 + 512) * 4)

__global__ __launch_bounds__(256)
void fc1_mma_kernel(const float* __restrict__ x, const float* __restrict__ b1)
{
    extern __shared__ __align__(16) float sm[];
    float* a_s    = sm;                               // [2][128][36] (pair-permuted k)
    float* b_s    = sm + FC1_A_FL;                    // [2][32][36]  (pair-permuted k)
    float* bias_s = sm + FC1_A_FL + FC1_B_FL;         // [32]
    float* red    = bias_s + 32;                      // [2][256]

    const int tid  = threadIdx.x;
    const int wid  = tid >> 5;
    const int lane = tid & 31;
    const int g    = lane >> 2;
    const int tg   = lane & 3;
    const size_t rowBase = (size_t)blockIdx.x * 128;

    if (tid < 32) bias_s[tid] = (tid < HH) ? b1[tid] : 0.f;

    float c[4][4];
    #pragma unroll
    for (int nt = 0; nt < 4; nt++)
        #pragma unroll
        for (int q = 0; q < 4; q++) c[nt][q] = 0.f;

    const int ar = tid >> 1;             // A row 0..127 (2 threads/row)
    const int kb = (tid & 1) * 16;       // k base: 0 or 16
    const int bn = tid >> 3;             // B: n 0..31
    const int bf = tid & 7;              // B: float4 idx 0..7
    float4 pfa4[4];                      // static-indexed only
    float4 pfb;

    auto prefetch = [&](int j) {
        const float* xp = &x[(rowBase + ar) * (size_t)N_IN + j * 32 + kb];
        #pragma unroll
        for (int q = 0; q < 4; q++) pfa4[q] = *(const float4*)(xp + q * 4);
        const float4* wb = (const float4*)g_w1t;     // per n: N_IN/4 float4
        pfb = wb[(size_t)bn * (N_IN / 4) + j * 8 + bf];
    };
    auto store_stage = [&](int st) {
        float* ap = &a_s[st * 4608 + ar * 36];
        float v[16];
        #pragma unroll
        for (int q = 0; q < 4; q++) {
            v[q*4+0] = pfa4[q].x; v[q*4+1] = pfa4[q].y;
            v[q*4+2] = pfa4[q].z; v[q*4+3] = pfa4[q].w;
        }
        #pragma unroll
        for (int grp = 0; grp < 2; grp++) {
            int ksab = (kb >> 3) + grp;
            #pragma unroll
            for (int t2 = 0; t2 < 4; t2++) {
                float2 w2 = make_float2(cvt_tf32f(v[grp*8 + t2]),
                                        cvt_tf32f(v[grp*8 + t2 + 4]));
                *(float2*)&ap[ksab * 8 + t2 * 2] = w2;
            }
        }
        *(float4*)&b_s[st * 1152 + bn * 36 + bf * 4] = pfb;
    };

    prefetch(0);
    store_stage(0);
    __syncthreads();
    prefetch(1);

    const int mr = wid * 16;
    for (int j = 0; j < 64; j++) {
        const int cur = j & 1, nxt = cur ^ 1;
        if (j < 63) store_stage(nxt);
        if (j < 62) prefetch(j + 2);
        const float* ab  = &a_s[cur * 4608];
        const float* bbp = &b_s[cur * 1152];
        #pragma unroll
        for (int ks = 0; ks < 4; ks++) {
            const int k0 = ks * 8;
            float2 aL = *(const float2*)&ab[(mr + g    ) * 36 + k0 + tg * 2];
            float2 aH = *(const float2*)&ab[(mr + g + 8) * 36 + k0 + tg * 2];
            uint32_t a0 = __float_as_uint(aL.x);
            uint32_t a1 = __float_as_uint(aH.x);
            uint32_t a2 = __float_as_uint(aL.y);
            uint32_t a3 = __float_as_uint(aH.y);
            #pragma unroll
            for (int nt = 0; nt < 4; nt++) {
                float2 f = *(const float2*)&bbp[(nt*8 + g) * 36 + k0 + tg * 2];
                mma_tf32(c[nt][0], c[nt][1], c[nt][2], c[nt][3], a0, a1, a2, a3,
                         __float_as_uint(f.x), __float_as_uint(f.y));
            }
        }
        __syncthreads();
    }

    // epilogue: bias + ReLU + store + BN partials
    size_t r0 = rowBase + wid * 16 + g;
    size_t r1 = r0 + 8;
    #pragma unroll
    for (int nt = 0; nt < 4; nt++) {
        int col = nt * 8 + tg * 2;
        float v00 = 0.f, v01 = 0.f, v10 = 0.f, v11 = 0.f;
        if (col < HH) {
            v00 = fmaxf(c[nt][0] + bias_s[col],     0.f);
            v01 = fmaxf(c[nt][1] + bias_s[col + 1], 0.f);
            v10 = fmaxf(c[nt][2] + bias_s[col],     0.f);
            v11 = fmaxf(c[nt][3] + bias_s[col + 1], 0.f);
            *(float2*)&g_flat[r0 * HH + col] = make_float2(v00, v01);
            *(float2*)&g_flat[r1 * HH + col] = make_float2(v10, v11);
        }
        float s0 = v00 + v10, q0 = v00 * v00 + v10 * v10;
        float s1 = v01 + v11, q1 = v01 * v01 + v11 * v11;
        #pragma unroll
        for (int off = 4; off < 32; off <<= 1) {
            s0 += __shfl_xor_sync(0xffffffffu, s0, off);
            q0 += __shfl_xor_sync(0xffffffffu, q0, off);
            s1 += __shfl_xor_sync(0xffffffffu, s1, off);
            q1 += __shfl_xor_sync(0xffffffffu, q1, off);
        }
        if (g == 0) {
            red[(col    ) * 8 + wid]       = s0;
            red[(col + 1) * 8 + wid]       = s1;
            red[256 + (col    ) * 8 + wid] = q0;
            red[256 + (col + 1) * 8 + wid] = q1;
        }
    }
    __syncthreads();
    if (tid < HH) {
        float s = 0.f, q = 0.f;
        #pragma unroll
        for (int w = 0; w < 8; w++) { s += red[tid * 8 + w]; q += red[256 + tid * 8 + w]; }
        g_partial[blockIdx.x * 60 + tid]      = s;
        g_partial[blockIdx.x * 60 + 30 + tid] = q;
    }
}

// ---------------- BN finalize ----------------
__global__ void bn_stats_kernel()
{
    __shared__ float rs[2][HH][9];
    int c = threadIdx.x & 31;
    int g = threadIdx.x >> 5;
    if (c < HH) {
        float s = 0.f, q = 0.f;
        for (int p = g; p < 1024; p += 8) {
            s += g_partial[p * 60 + c];
            q += g_partial[p * 60 + 30 + c];
        }
        rs[0][c][g] = s; rs[1][c][g] = q;
    }
    __syncthreads();
    if (threadIdx.x < HH) {
        float s = 0.f, q = 0.f;
        #pragma unroll
        for (int g2 = 0; g2 < 8; g2++) { s += rs[0][threadIdx.x][g2]; q += rs[1][threadIdx.x][g2]; }
        const float n = (float)ROWS;
        float mu  = s / n;
        float var = q / n - mu * mu;
        g_mu[threadIdx.x]   = mu;
        g_rstd[threadIdx.x] = rsqrtf(var + 1e-5f);
    }
}

// ---------------- LSTM (R6-proven: scalar dots + MUFU tanh) ----------------
#define LSTM_THREADS 256
#define LSTM_SMEM_FLOATS (SS*32 + 32 + 32 + 32 + 128 + 128 + 32 + 32)
#define LSTM_SMEM_BYTES  (LSTM_SMEM_FLOATS * 4)

__device__ __forceinline__ float dot_step(const float* __restrict__ xv,
                                          const float* __restrict__ hv,
                                          const float (&wi)[32], const float (&wh)[32],
                                          float bj)
{
    const float4* x4 = (const float4*)xv;
    const float4* h4 = (const float4*)hv;
    float a0 = bj, a1 = 0.f, a2 = 0.f, a3 = 0.f;
    float b0 = 0.f, b1 = 0.f, b2 = 0.f, b3 = 0.f;
    #pragma unroll
    for (int q = 0; q < 8; q++) {
        float4 xq = x4[q];
        a0 += wi[4*q+0] * xq.x; a1 += wi[4*q+1] * xq.y;
        a2 += wi[4*q+2] * xq.z; a3 += wi[4*q+3] * xq.w;
        float4 hq = h4[q];
        b0 += wh[4*q+0] * hq.x; b1 += wh[4*q+1] * hq.y;
        b2 += wh[4*q+2] * hq.z; b3 += wh[4*q+3] * hq.w;
    }
    return ((a0 + a1) + (a2 + a3)) + ((b0 + b1) + (b2 + b3));
}

__global__ __launch_bounds__(LSTM_THREADS, 2)
void lstm_kernel(const float* __restrict__ h0, const float* __restrict__ c0,
                 const float* __restrict__ Wih0, const float* __restrict__ Whh0,
                 const float* __restrict__ bias0,
                 const float* __restrict__ Wih1, const float* __restrict__ Whh1,
                 const float* __restrict__ bias1,
                 float* __restrict__ rnn_out)
{
    extern __shared__ __align__(16) float lsm[];
    float* xs    = lsm;                    // [512][32]
    float* h0s   = lsm + SS * 32;          // [32]
    float* h1s   = h0s + 32;               // [32]
    float* y0s   = h1s + 32;               // [32]
    float* z0s   = y0s + 32;               // [128]
    float* z1s   = z0s + 128;              // [128]
    float* mus   = z1s + 128;              // [32]
    float* rstds = mus + 32;               // [32]

    const int tid = threadIdx.x;
    const int b   = blockIdx.x;

    if (tid < 32) {
        mus[tid]   = (tid < HH) ? g_mu[tid]   : 0.f;
        rstds[tid] = (tid < HH) ? g_rstd[tid] : 0.f;
        h0s[tid] = (tid < HH) ? h0[b * HH + tid]            : 0.f;
        h1s[tid] = (tid < HH) ? h0[BB * HH + b * HH + tid]  : 0.f;
        y0s[tid] = 0.f;
    }
    __syncthreads();

    const float* fb = g_flat + (size_t)b * (SS * HH);
    for (int i = tid; i < SS * 32; i += LSTM_THREADS) {
        int s = i >> 5, k = i & 31;
        xs[i] = (k < HH) ? (fb[s * HH + k] - mus[k]) * rstds[k] : 0.f;
    }

    float wi[32], wh[32];
    float bj = 0.f;
    #pragma unroll
    for (int k = 0; k < 32; k++) { wi[k] = 0.f; wh[k] = 0.f; }
    if (tid < 120) {
        #pragma unroll
        for (int k = 0; k < HH; k++) {
            wi[k] = Wih0[tid * HH + k];
            wh[k] = Whh0[tid * HH + k];
        }
        bj = bias0[tid];
    } else if (tid >= 128 && tid < 248) {
        int j = tid - 128;
        #pragma unroll
        for (int k = 0; k < HH; k++) {
            wi[k] = Wih1[j * HH + k];
            wh[k] = Whh1[j * HH + k];
        }
        bj = bias1[j];
    }

    float creg = 0.f;
    if (tid < HH)                          creg = c0[b * HH + tid];
    else if (tid >= 128 && tid < 128+HH)   creg = c0[BB * HH + b * HH + (tid - 128)];

    __syncthreads();

    for (int t = 0; t <= SS; t++) {
        if (t < SS && tid < 120) {
            z0s[tid] = dot_step(xs + t * 32, h0s, wi, wh, bj);
        } else if (t >= 1 && tid >= 128 && tid < 248) {
            z1s[tid - 128] = dot_step(y0s, h1s, wi, wh, bj);
        }
        __syncthreads();
        if (t < SS && tid < HH) {
            float ig = hsig(z0s[tid]);
            float fg = hsig(z0s[30 + tid]);
            float gg = htanh(z0s[60 + tid]);
            float og = hsig(z0s[90 + tid]);
            creg = fg * creg + ig * gg;
            float hh = og * htanh(creg);
            h0s[tid] = hh;
            y0s[tid] = hh;
        } else if (t >= 1 && tid >= 128 && tid < 128 + HH) {
            int u = tid - 128;
            float ig = hsig(z1s[u]);
            float fg = hsig(z1s[30 + u]);
            float gg = htanh(z1s[60 + u]);
            float og = hsig(z1s[90 + u]);
            creg = fg * creg + ig * gg;
            float hh = og * htanh(creg);
            h1s[u] = hh;
            rnn_out[((size_t)b * SS + (t - 1)) * HH + u] = hh;
        }
        __syncthreads();
    }
}

// ================= output GEMM: tf32 mma.sync, 128x128 tiles =================
#define OG_A_FL (128*36)
#define OG_B_FL (128*36)
#define OG_SMEM_BYTES ((OG_A_FL + OG_B_FL) * 4)

__global__ __launch_bounds__(256)
void out_mma_kernel(const float* __restrict__ rnn, const float* __restrict__ bout,
                    float* __restrict__ dorsal)
{
    extern __shared__ __align__(16) float sm[];
    float* a_s = sm;                 // [128][36] (pair-permuted k)
    float* b_s = sm + OG_A_FL;       // [128][36] (pair-permuted k)

    const int tid  = threadIdx.x;
    const int wid  = tid >> 5;
    const int lane = tid & 31;
    const int g    = lane >> 2;
    const int tg   = lane & 3;
    const size_t rb = (size_t)(blockIdx.x >> 2) * 128;
    const int cb    = (blockIdx.x & 3) * 128;

    // A: rnn rows, k padded 30->32, tf32, pair-permuted positions
    for (int i = tid; i < 128 * 32; i += 256) {
        int r = i >> 5, k = i & 31;
        float v = (k < HH) ? rnn[(rb + r) * HH + k] : 0.f;
        a_s[r * 36 + kperm(k)] = cvt_tf32f(v);
    }
    {
        const float4* wb = (const float4*)g_wot;   // 8 float4 per n (already permuted)
        #pragma unroll
        for (int q = 0; q < 4; q++) {
            int idx = q * 256 + tid;               // 0..1023
            int n = idx >> 3, fi = idx & 7;
            float4 v = wb[(size_t)(cb + n) * 8 + fi];
            *(float4*)&b_s[n * 36 + fi * 4] = v;
        }
    }

    float c[16][4];
    #pragma unroll
    for (int nt = 0; nt < 16; nt++) {
        float bv0 = bout[cb + nt * 8 + tg * 2];
        float bv1 = bout[cb + nt * 8 + tg * 2 + 1];
        c[nt][0] = bv0; c[nt][1] = bv1; c[nt][2] = bv0; c[nt][3] = bv1;
    }
    __syncthreads();

    const int mr = wid * 16;
    #pragma unroll
    for (int ks = 0; ks < 4; ks++) {
        const int k0 = ks * 8;
        float2 aL = *(const float2*)&a_s[(mr + g    ) * 36 + k0 + tg * 2];
        float2 aH = *(const float2*)&a_s[(mr + g + 8) * 36 + k0 + tg * 2];
        uint32_t a0 = __float_as_uint(aL.x);
        uint32_t a1 = __float_as_uint(aH.x);
        uint32_t a2 = __float_as_uint(aL.y);
        uint32_t a3 = __float_as_uint(aH.y);
        #pragma unroll
        for (int nt = 0; nt < 16; nt++) {
            float2 f = *(const float2*)&b_s[(nt*8 + g) * 36 + k0 + tg * 2];
            mma_tf32(c[nt][0], c[nt][1], c[nt][2], c[nt][3], a0, a1, a2, a3,
                     __float_as_uint(f.x), __float_as_uint(f.y));
        }
    }

    size_t r0 = rb + wid * 16 + g;
    size_t r1 = r0 + 8;
    #pragma unroll
    for (int nt = 0; nt < 16; nt++) {
        int col = cb + nt * 8 + tg * 2;
        *(float2*)&dorsal[r0 * N_OUT + col] = make_float2(c[nt][0], c[nt][1]);
        *(float2*)&dorsal[r1 * N_OUT + col] = make_float2(c[nt][2], c[nt][3]);
    }
}

// ---------------- launch ----------------
extern "C" void kernel_launch(void* const* d_in, const int* in_sizes, int n_in,
                              void* d_out, int out_size)
{
    const float* x     = (const float*)d_in[0];
    const float* h0    = (const float*)d_in[1];
    const float* c0    = (const float*)d_in[2];
    const float* W1    = (const float*)d_in[3];
    const float* b1    = (const float*)d_in[4];
    const float* Wih0  = (const float*)d_in[5];
    const float* Whh0  = (const float*)d_in[6];
    const float* bias0 = (const float*)d_in[7];
    const float* Wih1  = (const float*)d_in[8];
    const float* Whh1  = (const float*)d_in[9];
    const float* bias1 = (const float*)d_in[10];
    const float* Wout  = (const float*)d_in[11];
    const float* bout  = (const float*)d_in[12];

    float* out    = (float*)d_out;
    float* dorsal = out;
    float* rnn    = out + (size_t)ROWS * N_OUT;

    cudaFuncSetAttribute(fc1_mma_kernel, cudaFuncAttributeMaxDynamicSharedMemorySize,
                         FC1_SMEM_BYTES);
    cudaFuncSetAttribute(out_mma_kernel, cudaFuncAttributeMaxDynamicSharedMemorySize,
                         OG_SMEM_BYTES);
    cudaFuncSetAttribute(lstm_kernel, cudaFuncAttributeMaxDynamicSharedMemorySize,
                         LSTM_SMEM_BYTES);

    prep_w_kernel<<<(32 * N_IN + N_OUT * 32) / 256, 256>>>(W1, Wout);
    fc1_mma_kernel<<<ROWS / 128, 256, FC1_SMEM_BYTES>>>(x, b1);
    bn_stats_kernel<<<1, 256>>>();
    lstm_kernel<<<BB, LSTM_THREADS, LSTM_SMEM_BYTES>>>(h0, c0, Wih0, Whh0, bias0,
                                                       Wih1, Whh1, bias1, rnn);
    out_mma_kernel<<<(ROWS / 128) * (N_OUT / 128), 256, OG_SMEM_BYTES>>>(rnn, bout, dorsal);
}

// round 11
// speedup vs baseline: 1.3059x; 1.1026x over previous
#include <cuda_runtime.h>
#include <cstdint>

#define BB 256
#define SS 512
#define N_IN 2048
#define N_OUT 512
#define HH 30
#define ROWS (BB*SS)   // 131072

// ---------------- device scratch ----------------
__device__ float g_flat[(size_t)ROWS * HH];
__device__ float g_partial[1024 * 64];
__device__ float g_mu[HH];
__device__ float g_rstd[HH];
// pre-converted weights (single rna-tf32), transposed [n][k]
__device__ uint32_t g_w1t[32 * N_IN];      // 256 KB
__device__ uint32_t g_wot[N_OUT * 32];     // 64 KB

// ---------------- helpers ----------------
__device__ __forceinline__ uint32_t smem_u32(const void* p) {
    uint32_t a;
    asm("{ .reg .u64 t; cvta.to.shared.u64 t, %1; cvt.u32.u64 %0, t; }" : "=r"(a) : "l"(p));
    return a;
}
__device__ __forceinline__ void cpasync16(uint32_t dst, const void* src) {
    asm volatile("cp.async.cg.shared.global [%0], [%1], 16;" :: "r"(dst), "l"(src));
}
__device__ __forceinline__ uint32_t cvt_tf32(float f) {
    uint32_t u; asm("cvt.rna.tf32.f32 %0, %1;" : "=r"(u) : "f"(f)); return u;
}
__device__ __forceinline__ void mma_tf32(float& c0, float& c1, float& c2, float& c3,
                                         uint32_t a0, uint32_t a1, uint32_t a2, uint32_t a3,
                                         uint32_t b0, uint32_t b1) {
    asm volatile(
        "mma.sync.aligned.m16n8k8.row.col.f32.tf32.tf32.f32 "
        "{%0,%1,%2,%3},{%4,%5,%6,%7},{%8,%9},{%0,%1,%2,%3};"
        : "+f"(c0), "+f"(c1), "+f"(c2), "+f"(c3)
        : "r"(a0), "r"(a1), "r"(a2), "r"(a3), "r"(b0), "r"(b1));
}
__device__ __forceinline__ float htanh(float x) {
    float r; asm("tanh.approx.f32 %0,%1;" : "=f"(r) : "f"(x)); return r;
}
__device__ __forceinline__ float hsig(float x) {
    return fmaf(htanh(x * 0.5f), 0.5f, 0.5f);
}

// ---------------- prep: W1/Wout -> tf32 (rna), transposed [n][k] ----------
__global__ __launch_bounds__(256)
void prep_w_kernel(const float* __restrict__ W1, const float* __restrict__ Wout)
{
    int i = blockIdx.x * 256 + threadIdx.x;
    if (i < 32 * N_IN) {
        int k = i >> 5, n = i & 31;
        float w = (n < HH) ? W1[(size_t)k * HH + n] : 0.f;
        g_w1t[n * N_IN + k] = cvt_tf32(w);
    }
    int j = i - 32 * N_IN;
    if (j >= 0 && j < N_OUT * 32) {
        int n = j >> 5, k = j & 31;
        float w = (k < HH) ? Wout[(size_t)k * N_OUT + n] : 0.f;
        g_wot[n * 32 + k] = cvt_tf32(w);
    }
}

// ================= fc1: tf32 mma.sync, cp.async 3-stage pipeline =============
// C[131072,30] = X @ W1; +bias, ReLU, BN partials.
// smem (floats): A[3][128][36] | B[3][32][36] | bias[32] | red[2*256]
#define FC1_STAGES 3
#define FC1_A_FL (FC1_STAGES*128*36)
#define FC1_B_FL (FC1_STAGES*32*36)
#define FC1_SMEM_BYTES ((FC1_A_FL + FC1_B_FL + 32 + 512) * 4)

__global__ __launch_bounds__(256)
void fc1_mma_kernel(const float* __restrict__ x, const float* __restrict__ b1)
{
    extern __shared__ __align__(16) float sm[];
    float* a_s    = sm;                               // [3][128][36]
    float* b_s    = sm + FC1_A_FL;                    // [3][32][36]
    float* bias_s = sm + FC1_A_FL + FC1_B_FL;         // [32]
    float* red    = bias_s + 32;                      // [2][256]
    const uint32_t a_u = smem_u32(a_s);
    const uint32_t b_u = smem_u32(b_s);

    const int tid  = threadIdx.x;
    const int wid  = tid >> 5;
    const int lane = tid & 31;
    const int g    = lane >> 2;
    const int tg   = lane & 3;
    const size_t rowBase = (size_t)blockIdx.x * 128;

    if (tid < 32) bias_s[tid] = (tid < HH) ? b1[tid] : 0.f;

    float c[4][4];
    #pragma unroll
    for (int nt = 0; nt < 4; nt++)
        #pragma unroll
        for (int q = 0; q < 4; q++) c[nt][q] = 0.f;

    const int ar = tid >> 1;             // A row 0..127 (2 threads/row)
    const int kb = (tid & 1) * 16;       // k base: 0 or 16
    const int bn = tid >> 3;             // B: n 0..31
    const int bf = tid & 7;              // B: float4 idx 0..7

    const float* xrow = &x[(rowBase + ar) * (size_t)N_IN + kb];
    const uint32_t* wrow = g_w1t + bn * N_IN + bf * 4;

    // issue cp.async for chunk j into stage st, then commit group
    auto load_chunk = [&](int j, int st) {
        uint32_t ad = a_u + (uint32_t)(st * 4608 + ar * 36 + kb) * 4;
        const float* xp = xrow + j * 32;
        cpasync16(ad,      xp);
        cpasync16(ad + 16, xp + 4);
        cpasync16(ad + 32, xp + 8);
        cpasync16(ad + 48, xp + 12);
        uint32_t bd = b_u + (uint32_t)(st * 1152 + bn * 36 + bf * 4) * 4;
        cpasync16(bd, wrow + j * 32);
    };

    load_chunk(0, 0); asm volatile("cp.async.commit_group;" ::: "memory");
    load_chunk(1, 1); asm volatile("cp.async.commit_group;" ::: "memory");
    load_chunk(2, 2); asm volatile("cp.async.commit_group;" ::: "memory");

    const int mr = wid * 16;
    int st = 0;
    for (int j = 0; j < 64; j++) {
        asm volatile("cp.async.wait_group 2;" ::: "memory");   // chunk j landed
        __syncthreads();
        const float* ab  = &a_s[st * 4608];
        const float* bbp = &b_s[st * 1152];
        #pragma unroll
        for (int ks = 0; ks < 4; ks++) {
            const int k0 = ks * 8;
            // A = raw f32 bits (HW truncates to tf32); B = rna tf32 (preconverted)
            uint32_t a0 = __float_as_uint(ab[(mr + g    ) * 36 + k0 + tg    ]);
            uint32_t a1 = __float_as_uint(ab[(mr + g + 8) * 36 + k0 + tg    ]);
            uint32_t a2 = __float_as_uint(ab[(mr + g    ) * 36 + k0 + tg + 4]);
            uint32_t a3 = __float_as_uint(ab[(mr + g + 8) * 36 + k0 + tg + 4]);
            #pragma unroll
            for (int nt = 0; nt < 4; nt++) {
                uint32_t b0 = __float_as_uint(bbp[(nt*8 + g) * 36 + k0 + tg    ]);
                uint32_t b1 = __float_as_uint(bbp[(nt*8 + g) * 36 + k0 + tg + 4]);
                mma_tf32(c[nt][0], c[nt][1], c[nt][2], c[nt][3], a0, a1, a2, a3, b0, b1);
            }
        }
        __syncthreads();
        if (j < 61) load_chunk(j + 3, st);
        asm volatile("cp.async.commit_group;" ::: "memory");   // (possibly empty) keeps group order
        st = (st == 2) ? 0 : st + 1;
    }

    // epilogue: bias + ReLU + store + BN partials
    size_t r0 = rowBase + wid * 16 + g;
    size_t r1 = r0 + 8;
    #pragma unroll
    for (int nt = 0; nt < 4; nt++) {
        int col = nt * 8 + tg * 2;
        float v00 = 0.f, v01 = 0.f, v10 = 0.f, v11 = 0.f;
        if (col < HH) {
            v00 = fmaxf(c[nt][0] + bias_s[col],     0.f);
            v01 = fmaxf(c[nt][1] + bias_s[col + 1], 0.f);
            v10 = fmaxf(c[nt][2] + bias_s[col],     0.f);
            v11 = fmaxf(c[nt][3] + bias_s[col + 1], 0.f);
            *(float2*)&g_flat[r0 * HH + col] = make_float2(v00, v01);
            *(float2*)&g_flat[r1 * HH + col] = make_float2(v10, v11);
        }
        float s0 = v00 + v10, q0 = v00 * v00 + v10 * v10;
        float s1 = v01 + v11, q1 = v01 * v01 + v11 * v11;
        #pragma unroll
        for (int off = 4; off < 32; off <<= 1) {
            s0 += __shfl_xor_sync(0xffffffffu, s0, off);
            q0 += __shfl_xor_sync(0xffffffffu, q0, off);
            s1 += __shfl_xor_sync(0xffffffffu, s1, off);
            q1 += __shfl_xor_sync(0xffffffffu, q1, off);
        }
        if (g == 0) {
            red[(col    ) * 8 + wid]       = s0;
            red[(col + 1) * 8 + wid]       = s1;
            red[256 + (col    ) * 8 + wid] = q0;
            red[256 + (col + 1) * 8 + wid] = q1;
        }
    }
    __syncthreads();
    if (tid < HH) {
        float s = 0.f, q = 0.f;
        #pragma unroll
        for (int w = 0; w < 8; w++) { s += red[tid * 8 + w]; q += red[256 + tid * 8 + w]; }
        g_partial[blockIdx.x * 60 + tid]      = s;
        g_partial[blockIdx.x * 60 + 30 + tid] = q;
    }
}

// ---------------- BN finalize ----------------
__global__ void bn_stats_kernel()
{
    __shared__ float rs[2][HH][9];
    int c = threadIdx.x & 31;
    int g = threadIdx.x >> 5;
    if (c < HH) {
        float s = 0.f, q = 0.f;
        for (int p = g; p < 1024; p += 8) {
            s += g_partial[p * 60 + c];
            q += g_partial[p * 60 + 30 + c];
        }
        rs[0][c][g] = s; rs[1][c][g] = q;
    }
    __syncthreads();
    if (threadIdx.x < HH) {
        float s = 0.f, q = 0.f;
        #pragma unroll
        for (int g2 = 0; g2 < 8; g2++) { s += rs[0][threadIdx.x][g2]; q += rs[1][threadIdx.x][g2]; }
        const float n = (float)ROWS;
        float mu  = s / n;
        float var = q / n - mu * mu;
        g_mu[threadIdx.x]   = mu;
        g_rstd[threadIdx.x] = rsqrtf(var + 1e-5f);
    }
}

// ---------------- LSTM (R6-proven: scalar dots + MUFU tanh) ----------------
#define LSTM_THREADS 256
#define LSTM_SMEM_FLOATS (SS*32 + 32 + 32 + 32 + 128 + 128 + 32 + 32)
#define LSTM_SMEM_BYTES  (LSTM_SMEM_FLOATS * 4)

__device__ __forceinline__ float dot_step(const float* __restrict__ xv,
                                          const float* __restrict__ hv,
                                          const float (&wi)[32], const float (&wh)[32],
                                          float bj)
{
    const float4* x4 = (const float4*)xv;
    const float4* h4 = (const float4*)hv;
    float a0 = bj, a1 = 0.f, a2 = 0.f, a3 = 0.f;
    float b0 = 0.f, b1 = 0.f, b2 = 0.f, b3 = 0.f;
    #pragma unroll
    for (int q = 0; q < 8; q++) {
        float4 xq = x4[q];
        a0 += wi[4*q+0] * xq.x; a1 += wi[4*q+1] * xq.y;
        a2 += wi[4*q+2] * xq.z; a3 += wi[4*q+3] * xq.w;
        float4 hq = h4[q];
        b0 += wh[4*q+0] * hq.x; b1 += wh[4*q+1] * hq.y;
        b2 += wh[4*q+2] * hq.z; b3 += wh[4*q+3] * hq.w;
    }
    return ((a0 + a1) + (a2 + a3)) + ((b0 + b1) + (b2 + b3));
}

__global__ __launch_bounds__(LSTM_THREADS, 2)
void lstm_kernel(const float* __restrict__ h0, const float* __restrict__ c0,
                 const float* __restrict__ Wih0, const float* __restrict__ Whh0,
                 const float* __restrict__ bias0,
                 const float* __restrict__ Wih1, const float* __restrict__ Whh1,
                 const float* __restrict__ bias1,
                 float* __restrict__ rnn_out)
{
    extern __shared__ __align__(16) float lsm[];
    float* xs    = lsm;                    // [512][32]
    float* h0s   = lsm + SS * 32;          // [32]
    float* h1s   = h0s + 32;               // [32]
    float* y0s   = h1s + 32;               // [32]
    float* z0s   = y0s + 32;               // [128]
    float* z1s   = z0s + 128;              // [128]
    float* mus   = z1s + 128;              // [32]
    float* rstds = mus + 32;               // [32]

    const int tid = threadIdx.x;
    const int b   = blockIdx.x;

    if (tid < 32) {
        mus[tid]   = (tid < HH) ? g_mu[tid]   : 0.f;
        rstds[tid] = (tid < HH) ? g_rstd[tid] : 0.f;
        h0s[tid] = (tid < HH) ? h0[b * HH + tid]            : 0.f;
        h1s[tid] = (tid < HH) ? h0[BB * HH + b * HH + tid]  : 0.f;
        y0s[tid] = 0.f;
    }
    __syncthreads();

    const float* fb = g_flat + (size_t)b * (SS * HH);
    for (int i = tid; i < SS * 32; i += LSTM_THREADS) {
        int s = i >> 5, k = i & 31;
        xs[i] = (k < HH) ? (fb[s * HH + k] - mus[k]) * rstds[k] : 0.f;
    }

    float wi[32], wh[32];
    float bj = 0.f;
    #pragma unroll
    for (int k = 0; k < 32; k++) { wi[k] = 0.f; wh[k] = 0.f; }
    if (tid < 120) {
        #pragma unroll
        for (int k = 0; k < HH; k++) {
            wi[k] = Wih0[tid * HH + k];
            wh[k] = Whh0[tid * HH + k];
        }
        bj = bias0[tid];
    } else if (tid >= 128 && tid < 248) {
        int j = tid - 128;
        #pragma unroll
        for (int k = 0; k < HH; k++) {
            wi[k] = Wih1[j * HH + k];
            wh[k] = Whh1[j * HH + k];
        }
        bj = bias1[j];
    }

    float creg = 0.f;
    if (tid < HH)                          creg = c0[b * HH + tid];
    else if (tid >= 128 && tid < 128+HH)   creg = c0[BB * HH + b * HH + (tid - 128)];

    __syncthreads();

    for (int t = 0; t <= SS; t++) {
        if (t < SS && tid < 120) {
            z0s[tid] = dot_step(xs + t * 32, h0s, wi, wh, bj);
        } else if (t >= 1 && tid >= 128 && tid < 248) {
            z1s[tid - 128] = dot_step(y0s, h1s, wi, wh, bj);
        }
        __syncthreads();
        if (t < SS && tid < HH) {
            float ig = hsig(z0s[tid]);
            float fg = hsig(z0s[30 + tid]);
            float gg = htanh(z0s[60 + tid]);
            float og = hsig(z0s[90 + tid]);
            creg = fg * creg + ig * gg;
            float hh = og * htanh(creg);
            h0s[tid] = hh;
            y0s[tid] = hh;
        } else if (t >= 1 && tid >= 128 && tid < 128 + HH) {
            int u = tid - 128;
            float ig = hsig(z1s[u]);
            float fg = hsig(z1s[30 + u]);
            float gg = htanh(z1s[60 + u]);
            float og = hsig(z1s[90 + u]);
            creg = fg * creg + ig * gg;
            float hh = og * htanh(creg);
            h1s[u] = hh;
            rnn_out[((size_t)b * SS + (t - 1)) * HH + u] = hh;
        }
        __syncthreads();
    }
}

// ================= output GEMM: tf32 mma.sync, 128x128 tiles (R8) =============
#define OG_A_FL (128*36)
#define OG_B_FL (128*36)
#define OG_SMEM_BYTES ((OG_A_FL + OG_B_FL) * 4)

__global__ __launch_bounds__(256)
void out_mma_kernel(const float* __restrict__ rnn, const float* __restrict__ bout,
                    float* __restrict__ dorsal)
{
    extern __shared__ __align__(16) float sm[];
    float* a_s = sm;                 // [128][36]
    float* b_s = sm + OG_A_FL;       // [128][36]

    const int tid  = threadIdx.x;
    const int wid  = tid >> 5;
    const int lane = tid & 31;
    const int g    = lane >> 2;
    const int tg   = lane & 3;
    const size_t rb = (size_t)(blockIdx.x >> 2) * 128;
    const int cb    = (blockIdx.x & 3) * 128;

    for (int i = tid; i < 128 * 32; i += 256) {
        int r = i >> 5, k = i & 31;
        float v = (k < HH) ? rnn[(rb + r) * HH + k] : 0.f;
        a_s[r * 36 + k] = __uint_as_float(cvt_tf32(v));
    }
    {
        const float4* wb = (const float4*)g_wot;   // 8 float4 per n
        #pragma unroll
        for (int q = 0; q < 4; q++) {
            int idx = q * 256 + tid;               // 0..1023
            int n = idx >> 3, fi = idx & 7;
            float4 v = wb[(size_t)(cb + n) * 8 + fi];
            *(float4*)&b_s[n * 36 + fi * 4] = v;
        }
    }

    float c[16][4];
    #pragma unroll
    for (int nt = 0; nt < 16; nt++) {
        float bv0 = bout[cb + nt * 8 + tg * 2];
        float bv1 = bout[cb + nt * 8 + tg * 2 + 1];
        c[nt][0] = bv0; c[nt][1] = bv1; c[nt][2] = bv0; c[nt][3] = bv1;
    }
    __syncthreads();

    const int mr = wid * 16;
    #pragma unroll
    for (int ks = 0; ks < 4; ks++) {
        const int k0 = ks * 8;
        uint32_t a0 = __float_as_uint(a_s[(mr + g    ) * 36 + k0 + tg    ]);
        uint32_t a1 = __float_as_uint(a_s[(mr + g + 8) * 36 + k0 + tg    ]);
        uint32_t a2 = __float_as_uint(a_s[(mr + g    ) * 36 + k0 + tg + 4]);
        uint32_t a3 = __float_as_uint(a_s[(mr + g + 8) * 36 + k0 + tg + 4]);
        #pragma unroll
        for (int nt = 0; nt < 16; nt++) {
            uint32_t b0 = __float_as_uint(b_s[(nt*8 + g) * 36 + k0 + tg    ]);
            uint32_t b1 = __float_as_uint(b_s[(nt*8 + g) * 36 + k0 + tg + 4]);
            mma_tf32(c[nt][0], c[nt][1], c[nt][2], c[nt][3], a0, a1, a2, a3, b0, b1);
        }
    }

    size_t r0 = rb + wid * 16 + g;
    size_t r1 = r0 + 8;
    #pragma unroll
    for (int nt = 0; nt < 16; nt++) {
        int col = cb + nt * 8 + tg * 2;
        *(float2*)&dorsal[r0 * N_OUT + col] = make_float2(c[nt][0], c[nt][1]);
        *(float2*)&dorsal[r1 * N_OUT + col] = make_float2(c[nt][2], c[nt][3]);
    }
}

// ---------------- launch ----------------
extern "C" void kernel_launch(void* const* d_in, const int* in_sizes, int n_in,
                              void* d_out, int out_size)
{
    const float* x     = (const float*)d_in[0];
    const float* h0    = (const float*)d_in[1];
    const float* c0    = (const float*)d_in[2];
    const float* W1    = (const float*)d_in[3];
    const float* b1    = (const float*)d_in[4];
    const float* Wih0  = (const float*)d_in[5];
    const float* Whh0  = (const float*)d_in[6];
    const float* bias0 = (const float*)d_in[7];
    const float* Wih1  = (const float*)d_in[8];
    const float* Whh1  = (const float*)d_in[9];
    const float* bias1 = (const float*)d_in[10];
    const float* Wout  = (const float*)d_in[11];
    const float* bout  = (const float*)d_in[12];

    float* out    = (float*)d_out;
    float* dorsal = out;
    float* rnn    = out + (size_t)ROWS * N_OUT;

    cudaFuncSetAttribute(fc1_mma_kernel, cudaFuncAttributeMaxDynamicSharedMemorySize,
                         FC1_SMEM_BYTES);
    cudaFuncSetAttribute(out_mma_kernel, cudaFuncAttributeMaxDynamicSharedMemorySize,
                         OG_SMEM_BYTES);
    cudaFuncSetAttribute(lstm_kernel, cudaFuncAttributeMaxDynamicSharedMemorySize,
                         LSTM_SMEM_BYTES);

    prep_w_kernel<<<(32 * N_IN + N_OUT * 32) / 256, 256>>>(W1, Wout);
    fc1_mma_kernel<<<ROWS / 128, 256, FC1_SMEM_BYTES>>>(x, b1);
    bn_stats_kernel<<<1, 256>>>();
    lstm_kernel<<<BB, LSTM_THREADS, LSTM_SMEM_BYTES>>>(h0, c0, Wih0, Whh0, bias0,
                                                       Wih1, Whh1, bias1, rnn);
    out_mma_kernel<<<(ROWS / 128) * (N_OUT / 128), 256, OG_SMEM_BYTES>>>(rnn, bout, dorsal);
}

// round 12
// speedup vs baseline: 1.3153x; 1.0072x over previous
#include <cuda_runtime.h>
#include <cstdint>

#define BB 256
#define SS 512
#define N_IN 2048
#define N_OUT 512
#define HH 30
#define ROWS (BB*SS)   // 131072

// ---------------- device scratch ----------------
__device__ float g_flat[(size_t)ROWS * HH];
__device__ float g_partial[1024 * 64];
__device__ float g_mu[HH];
__device__ float g_rstd[HH];
// pre-converted weights (single rna-tf32), transposed [n][k]
__device__ uint32_t g_w1t[32 * N_IN];      // 256 KB
__device__ uint32_t g_wot[N_OUT * 32];     // 64 KB

// ---------------- helpers ----------------
__device__ __forceinline__ uint32_t cvt_tf32(float f) {
    uint32_t u; asm("cvt.rna.tf32.f32 %0, %1;" : "=r"(u) : "f"(f)); return u;
}
__device__ __forceinline__ void mma_tf32(float& c0, float& c1, float& c2, float& c3,
                                         uint32_t a0, uint32_t a1, uint32_t a2, uint32_t a3,
                                         uint32_t b0, uint32_t b1) {
    asm volatile(
        "mma.sync.aligned.m16n8k8.row.col.f32.tf32.tf32.f32 "
        "{%0,%1,%2,%3},{%4,%5,%6,%7},{%8,%9},{%0,%1,%2,%3};"
        : "+f"(c0), "+f"(c1), "+f"(c2), "+f"(c3)
        : "r"(a0), "r"(a1), "r"(a2), "r"(a3), "r"(b0), "r"(b1));
}
__device__ __forceinline__ float htanh(float x) {
    float r; asm("tanh.approx.f32 %0,%1;" : "=f"(r) : "f"(x)); return r;
}
__device__ __forceinline__ float hsig(float x) {
    return fmaf(htanh(x * 0.5f), 0.5f, 0.5f);
}

// ---------------- prep: W1/Wout -> tf32 (rna), transposed [n][k] ----------
__global__ __launch_bounds__(256)
void prep_w_kernel(const float* __restrict__ W1, const float* __restrict__ Wout)
{
    int i = blockIdx.x * 256 + threadIdx.x;
    if (i < 32 * N_IN) {
        int k = i >> 5, n = i & 31;
        float w = (n < HH) ? W1[(size_t)k * HH + n] : 0.f;
        g_w1t[n * N_IN + k] = cvt_tf32(w);
    }
    int j = i - 32 * N_IN;
    if (j >= 0 && j < N_OUT * 32) {
        int n = j >> 5, k = j & 31;
        float w = (k < HH) ? Wout[(size_t)k * N_OUT + n] : 0.f;
        g_wot[n * 32 + k] = cvt_tf32(w);
    }
}

// ================= fc1: tf32 mma.sync, double-buffered (R8 exact) ============
#define FC1_A_FL (2*128*36)
#define FC1_B_FL (2*32*36)
#define FC1_SMEM_BYTES ((FC1_A_FL + FC1_B_FL + 32 + 512) * 4)

__global__ __launch_bounds__(256)
void fc1_mma_kernel(const float* __restrict__ x, const float* __restrict__ b1)
{
    extern __shared__ __align__(16) float sm[];
    float* a_s    = sm;                               // [2][128][36]
    float* b_s    = sm + FC1_A_FL;                    // [2][32][36]
    float* bias_s = sm + FC1_A_FL + FC1_B_FL;         // [32]
    float* red    = bias_s + 32;                      // [2][256]

    const int tid  = threadIdx.x;
    const int wid  = tid >> 5;
    const int lane = tid & 31;
    const int g    = lane >> 2;
    const int tg   = lane & 3;
    const size_t rowBase = (size_t)blockIdx.x * 128;

    if (tid < 32) bias_s[tid] = (tid < HH) ? b1[tid] : 0.f;

    float c[4][4];
    #pragma unroll
    for (int nt = 0; nt < 4; nt++)
        #pragma unroll
        for (int q = 0; q < 4; q++) c[nt][q] = 0.f;

    const int ar = tid >> 1;             // A row 0..127 (2 threads/row)
    const int kb = (tid & 1) * 16;       // k base: 0 or 16
    const int bn = tid >> 3;             // B: n 0..31
    const int bf = tid & 7;              // B: float4 idx 0..7
    float4 pfa4[4];
    float4 pfb;

    auto prefetch = [&](int j) {
        const float* xp = &x[(rowBase + ar) * (size_t)N_IN + j * 32 + kb];
        #pragma unroll
        for (int q = 0; q < 4; q++) pfa4[q] = *(const float4*)(xp + q * 4);
        const float4* wb = (const float4*)g_w1t;     // per n: N_IN/4 float4
        pfb = wb[(size_t)bn * (N_IN / 4) + j * 8 + bf];
    };
    auto store_stage = [&](int st) {
        float* ap = &a_s[st * 4608 + ar * 36 + kb];
        #pragma unroll
        for (int q = 0; q < 4; q++) {
            ap[q*4+0] = __uint_as_float(cvt_tf32(pfa4[q].x));
            ap[q*4+1] = __uint_as_float(cvt_tf32(pfa4[q].y));
            ap[q*4+2] = __uint_as_float(cvt_tf32(pfa4[q].z));
            ap[q*4+3] = __uint_as_float(cvt_tf32(pfa4[q].w));
        }
        *(float4*)&b_s[st * 1152 + bn * 36 + bf * 4] = pfb;
    };

    prefetch(0);
    store_stage(0);
    __syncthreads();
    prefetch(1);

    const int mr = wid * 16;
    for (int j = 0; j < 64; j++) {
        const int cur = j & 1, nxt = cur ^ 1;
        if (j < 63) store_stage(nxt);
        if (j < 62) prefetch(j + 2);
        const float* ab  = &a_s[cur * 4608];
        const float* bbp = &b_s[cur * 1152];
        #pragma unroll
        for (int ks = 0; ks < 4; ks++) {
            const int k0 = ks * 8;
            uint32_t a0 = __float_as_uint(ab[(mr + g    ) * 36 + k0 + tg    ]);
            uint32_t a1 = __float_as_uint(ab[(mr + g + 8) * 36 + k0 + tg    ]);
            uint32_t a2 = __float_as_uint(ab[(mr + g    ) * 36 + k0 + tg + 4]);
            uint32_t a3 = __float_as_uint(ab[(mr + g + 8) * 36 + k0 + tg + 4]);
            #pragma unroll
            for (int nt = 0; nt < 4; nt++) {
                uint32_t b0 = __float_as_uint(bbp[(nt*8 + g) * 36 + k0 + tg    ]);
                uint32_t b1 = __float_as_uint(bbp[(nt*8 + g) * 36 + k0 + tg + 4]);
                mma_tf32(c[nt][0], c[nt][1], c[nt][2], c[nt][3], a0, a1, a2, a3, b0, b1);
            }
        }
        __syncthreads();
    }

    // epilogue: bias + ReLU + store + BN partials
    size_t r0 = rowBase + wid * 16 + g;
    size_t r1 = r0 + 8;
    #pragma unroll
    for (int nt = 0; nt < 4; nt++) {
        int col = nt * 8 + tg * 2;
        float v00 = 0.f, v01 = 0.f, v10 = 0.f, v11 = 0.f;
        if (col < HH) {
            v00 = fmaxf(c[nt][0] + bias_s[col],     0.f);
            v01 = fmaxf(c[nt][1] + bias_s[col + 1], 0.f);
            v10 = fmaxf(c[nt][2] + bias_s[col],     0.f);
            v11 = fmaxf(c[nt][3] + bias_s[col + 1], 0.f);
            *(float2*)&g_flat[r0 * HH + col] = make_float2(v00, v01);
            *(float2*)&g_flat[r1 * HH + col] = make_float2(v10, v11);
        }
        float s0 = v00 + v10, q0 = v00 * v00 + v10 * v10;
        float s1 = v01 + v11, q1 = v01 * v01 + v11 * v11;
        #pragma unroll
        for (int off = 4; off < 32; off <<= 1) {
            s0 += __shfl_xor_sync(0xffffffffu, s0, off);
            q0 += __shfl_xor_sync(0xffffffffu, q0, off);
            s1 += __shfl_xor_sync(0xffffffffu, s1, off);
            q1 += __shfl_xor_sync(0xffffffffu, q1, off);
        }
        if (g == 0) {
            red[(col    ) * 8 + wid]       = s0;
            red[(col + 1) * 8 + wid]       = s1;
            red[256 + (col    ) * 8 + wid] = q0;
            red[256 + (col + 1) * 8 + wid] = q1;
        }
    }
    __syncthreads();
    if (tid < HH) {
        float s = 0.f, q = 0.f;
        #pragma unroll
        for (int w = 0; w < 8; w++) { s += red[tid * 8 + w]; q += red[256 + tid * 8 + w]; }
        g_partial[blockIdx.x * 60 + tid]      = s;
        g_partial[blockIdx.x * 60 + 30 + tid] = q;
    }
}

// ---------------- BN finalize ----------------
__global__ void bn_stats_kernel()
{
    __shared__ float rs[2][HH][9];
    int c = threadIdx.x & 31;
    int g = threadIdx.x >> 5;
    if (c < HH) {
        float s = 0.f, q = 0.f;
        for (int p = g; p < 1024; p += 8) {
            s += g_partial[p * 60 + c];
            q += g_partial[p * 60 + 30 + c];
        }
        rs[0][c][g] = s; rs[1][c][g] = q;
    }
    __syncthreads();
    if (threadIdx.x < HH) {
        float s = 0.f, q = 0.f;
        #pragma unroll
        for (int g2 = 0; g2 < 8; g2++) { s += rs[0][threadIdx.x][g2]; q += rs[1][threadIdx.x][g2]; }
        const float n = (float)ROWS;
        float mu  = s / n;
        float var = q / n - mu * mu;
        g_mu[threadIdx.x]   = mu;
        g_rstd[threadIdx.x] = rsqrtf(var + 1e-5f);
    }
}

// ---------------- LSTM (R6-proven: scalar dots + MUFU tanh) ----------------
#define LSTM_THREADS 256
#define LSTM_SMEM_FLOATS (SS*32 + 32 + 32 + 32 + 128 + 128 + 32 + 32)
#define LSTM_SMEM_BYTES  (LSTM_SMEM_FLOATS * 4)

__device__ __forceinline__ float dot_step(const float* __restrict__ xv,
                                          const float* __restrict__ hv,
                                          const float (&wi)[32], const float (&wh)[32],
                                          float bj)
{
    const float4* x4 = (const float4*)xv;
    const float4* h4 = (const float4*)hv;
    float a0 = bj, a1 = 0.f, a2 = 0.f, a3 = 0.f;
    float b0 = 0.f, b1 = 0.f, b2 = 0.f, b3 = 0.f;
    #pragma unroll
    for (int q = 0; q < 8; q++) {
        float4 xq = x4[q];
        a0 += wi[4*q+0] * xq.x; a1 += wi[4*q+1] * xq.y;
        a2 += wi[4*q+2] * xq.z; a3 += wi[4*q+3] * xq.w;
        float4 hq = h4[q];
        b0 += wh[4*q+0] * hq.x; b1 += wh[4*q+1] * hq.y;
        b2 += wh[4*q+2] * hq.z; b3 += wh[4*q+3] * hq.w;
    }
    return ((a0 + a1) + (a2 + a3)) + ((b0 + b1) + (b2 + b3));
}

__global__ __launch_bounds__(LSTM_THREADS, 2)
void lstm_kernel(const float* __restrict__ h0, const float* __restrict__ c0,
                 const float* __restrict__ Wih0, const float* __restrict__ Whh0,
                 const float* __restrict__ bias0,
                 const float* __restrict__ Wih1, const float* __restrict__ Whh1,
                 const float* __restrict__ bias1,
                 float* __restrict__ rnn_out)
{
    extern __shared__ __align__(16) float lsm[];
    float* xs    = lsm;                    // [512][32]
    float* h0s   = lsm + SS * 32;          // [32]
    float* h1s   = h0s + 32;               // [32]
    float* y0s   = h1s + 32;               // [32]
    float* z0s   = y0s + 32;               // [128]
    float* z1s   = z0s + 128;              // [128]
    float* mus   = z1s + 128;              // [32]
    float* rstds = mus + 32;               // [32]

    const int tid = threadIdx.x;
    const int b   = blockIdx.x;

    if (tid < 32) {
        mus[tid]   = (tid < HH) ? g_mu[tid]   : 0.f;
        rstds[tid] = (tid < HH) ? g_rstd[tid] : 0.f;
        h0s[tid] = (tid < HH) ? h0[b * HH + tid]            : 0.f;
        h1s[tid] = (tid < HH) ? h0[BB * HH + b * HH + tid]  : 0.f;
        y0s[tid] = 0.f;
    }
    __syncthreads();

    const float* fb = g_flat + (size_t)b * (SS * HH);
    for (int i = tid; i < SS * 32; i += LSTM_THREADS) {
        int s = i >> 5, k = i & 31;
        xs[i] = (k < HH) ? (fb[s * HH + k] - mus[k]) * rstds[k] : 0.f;
    }

    float wi[32], wh[32];
    float bj = 0.f;
    #pragma unroll
    for (int k = 0; k < 32; k++) { wi[k] = 0.f; wh[k] = 0.f; }
    if (tid < 120) {
        #pragma unroll
        for (int k = 0; k < HH; k++) {
            wi[k] = Wih0[tid * HH + k];
            wh[k] = Whh0[tid * HH + k];
        }
        bj = bias0[tid];
    } else if (tid >= 128 && tid < 248) {
        int j = tid - 128;
        #pragma unroll
        for (int k = 0; k < HH; k++) {
            wi[k] = Wih1[j * HH + k];
            wh[k] = Whh1[j * HH + k];
        }
        bj = bias1[j];
    }

    float creg = 0.f;
    if (tid < HH)                          creg = c0[b * HH + tid];
    else if (tid >= 128 && tid < 128+HH)   creg = c0[BB * HH + b * HH + (tid - 128)];

    __syncthreads();

    for (int t = 0; t <= SS; t++) {
        if (t < SS && tid < 120) {
            z0s[tid] = dot_step(xs + t * 32, h0s, wi, wh, bj);
        } else if (t >= 1 && tid >= 128 && tid < 248) {
            z1s[tid - 128] = dot_step(y0s, h1s, wi, wh, bj);
        }
        __syncthreads();
        if (t < SS && tid < HH) {
            float ig = hsig(z0s[tid]);
            float fg = hsig(z0s[30 + tid]);
            float gg = htanh(z0s[60 + tid]);
            float og = hsig(z0s[90 + tid]);
            creg = fg * creg + ig * gg;
            float hh = og * htanh(creg);
            h0s[tid] = hh;
            y0s[tid] = hh;
        } else if (t >= 1 && tid >= 128 && tid < 128 + HH) {
            int u = tid - 128;
            float ig = hsig(z1s[u]);
            float fg = hsig(z1s[30 + u]);
            float gg = htanh(z1s[60 + u]);
            float og = hsig(z1s[90 + u]);
            creg = fg * creg + ig * gg;
            float hh = og * htanh(creg);
            h1s[u] = hh;
            rnn_out[((size_t)b * SS + (t - 1)) * HH + u] = hh;
        }
        __syncthreads();
    }
}

// ================= output GEMM: tf32 mma.sync, coalesced smem-staged stores ===
#define OG_A_FL (128*36)
#define OG_B_FL (128*36)
#define OG_SMEM_BYTES ((OG_A_FL + OG_B_FL) * 4)

__global__ __launch_bounds__(256)
void out_mma_kernel(const float* __restrict__ rnn, const float* __restrict__ bout,
                    float* __restrict__ dorsal)
{
    extern __shared__ __align__(16) float sm[];
    float* a_s = sm;                 // [128][36]
    float* b_s = sm + OG_A_FL;       // [128][36]
    float* c_s = sm;                 // epilogue staging [128][36] (reuses a_s)

    const int tid  = threadIdx.x;
    const int wid  = tid >> 5;
    const int lane = tid & 31;
    const int g    = lane >> 2;
    const int tg   = lane & 3;
    const size_t rb = (size_t)(blockIdx.x >> 2) * 128;
    const int cb    = (blockIdx.x & 3) * 128;

    for (int i = tid; i < 128 * 32; i += 256) {
        int r = i >> 5, k = i & 31;
        float v = (k < HH) ? rnn[(rb + r) * HH + k] : 0.f;
        a_s[r * 36 + k] = __uint_as_float(cvt_tf32(v));
    }
    {
        const float4* wb = (const float4*)g_wot;   // 8 float4 per n
        #pragma unroll
        for (int q = 0; q < 4; q++) {
            int idx = q * 256 + tid;               // 0..1023
            int n = idx >> 3, fi = idx & 7;
            float4 v = wb[(size_t)(cb + n) * 8 + fi];
            *(float4*)&b_s[n * 36 + fi * 4] = v;
        }
    }

    float c[16][4];
    #pragma unroll
    for (int nt = 0; nt < 16; nt++) {
        float bv0 = bout[cb + nt * 8 + tg * 2];
        float bv1 = bout[cb + nt * 8 + tg * 2 + 1];
        c[nt][0] = bv0; c[nt][1] = bv1; c[nt][2] = bv0; c[nt][3] = bv1;
    }
    __syncthreads();

    const int mr = wid * 16;
    #pragma unroll
    for (int ks = 0; ks < 4; ks++) {
        const int k0 = ks * 8;
        uint32_t a0 = __float_as_uint(a_s[(mr + g    ) * 36 + k0 + tg    ]);
        uint32_t a1 = __float_as_uint(a_s[(mr + g + 8) * 36 + k0 + tg    ]);
        uint32_t a2 = __float_as_uint(a_s[(mr + g    ) * 36 + k0 + tg + 4]);
        uint32_t a3 = __float_as_uint(a_s[(mr + g + 8) * 36 + k0 + tg + 4]);
        #pragma unroll
        for (int nt = 0; nt < 16; nt++) {
            uint32_t b0 = __float_as_uint(b_s[(nt*8 + g) * 36 + k0 + tg    ]);
            uint32_t b1 = __float_as_uint(b_s[(nt*8 + g) * 36 + k0 + tg + 4]);
            mma_tf32(c[nt][0], c[nt][1], c[nt][2], c[nt][3], a0, a1, a2, a3, b0, b1);
        }
    }

    // ---- coalesced epilogue: 4 chunks of 32 columns via smem staging ----
    const int srow = tid >> 3;          // 0..31 (base row for STG phase)
    const int sc4  = tid & 7;           // float4 col index 0..7
    #pragma unroll
    for (int q = 0; q < 4; q++) {
        __syncthreads();                // smem (a_s/b_s or prev chunk) free
        // scatter this chunk's accumulators: nt = 4q..4q+3, local col = (nt&3)*8+tg*2
        #pragma unroll
        for (int ntl = 0; ntl < 4; ntl++) {
            int nt = q * 4 + ntl;
            int lc = ntl * 8 + tg * 2;
            *(float2*)&c_s[(wid * 16 + g    ) * 36 + lc] = make_float2(c[nt][0], c[nt][1]);
            *(float2*)&c_s[(wid * 16 + g + 8) * 36 + lc] = make_float2(c[nt][2], c[nt][3]);
        }
        __syncthreads();
        // coalesced write: warp covers 4 rows x 128B contiguous
        #pragma unroll
        for (int p = 0; p < 4; p++) {
            int row = srow + p * 32;
            float4 v = *(const float4*)&c_s[row * 36 + sc4 * 4];
            *(float4*)&dorsal[(rb + row) * N_OUT + cb + q * 32 + sc4 * 4] = v;
        }
    }
}

// ---------------- launch ----------------
extern "C" void kernel_launch(void* const* d_in, const int* in_sizes, int n_in,
                              void* d_out, int out_size)
{
    const float* x     = (const float*)d_in[0];
    const float* h0    = (const float*)d_in[1];
    const float* c0    = (const float*)d_in[2];
    const float* W1    = (const float*)d_in[3];
    const float* b1    = (const float*)d_in[4];
    const float* Wih0  = (const float*)d_in[5];
    const float* Whh0  = (const float*)d_in[6];
    const float* bias0 = (const float*)d_in[7];
    const float* Wih1  = (const float*)d_in[8];
    const float* Whh1  = (const float*)d_in[9];
    const float* bias1 = (const float*)d_in[10];
    const float* Wout  = (const float*)d_in[11];
    const float* bout  = (const float*)d_in[12];

    float* out    = (float*)d_out;
    float* dorsal = out;
    float* rnn    = out + (size_t)ROWS * N_OUT;

    cudaFuncSetAttribute(fc1_mma_kernel, cudaFuncAttributeMaxDynamicSharedMemorySize,
                         FC1_SMEM_BYTES);
    cudaFuncSetAttribute(out_mma_kernel, cudaFuncAttributeMaxDynamicSharedMemorySize,
                         OG_SMEM_BYTES);
    cudaFuncSetAttribute(lstm_kernel, cudaFuncAttributeMaxDynamicSharedMemorySize,
                         LSTM_SMEM_BYTES);

    prep_w_kernel<<<(32 * N_IN + N_OUT * 32) / 256, 256>>>(W1, Wout);
    fc1_mma_kernel<<<ROWS / 128, 256, FC1_SMEM_BYTES>>>(x, b1);
    bn_stats_kernel<<<1, 256>>>();
    lstm_kernel<<<BB, LSTM_THREADS, LSTM_SMEM_BYTES>>>(h0, c0, Wih0, Whh0, bias0,
                                                       Wih1, Whh1, bias1, rnn);
    out_mma_kernel<<<(ROWS / 128) * (N_OUT / 128), 256, OG_SMEM_BYTES>>>(rnn, bout, dorsal);
}